// round 6
// baseline (speedup 1.0000x reference)
#include <cuda_runtime.h>

#define BB 16
#define NN 4096
#define SS 1024
#define KK 32
#define POSN (BB*SS*KK)          // 524288
#define XYZ_OUT (BB*3*SS)        // 49152

// ---------------- scratch (__device__ globals; no allocations) ----------------
__device__ float g_newxyz[BB][SS][3];
__device__ float g_G[6][POSN];          // grouped input, channel-major
__device__ float g_x0[64][POSN];        // layer0 pre-activation
__device__ float g_x1[64][POSN];        // layer1 pre-activation
__device__ float g_x2[128][POSN];       // layer2 pre-activation
__device__ float g_sum0[64], g_sq0[64];
__device__ float g_sum1[64], g_sq1[64];
__device__ float g_sum2[128], g_sq2[128];
__device__ float g_s0[64], g_t0[64];
__device__ float g_s1[64], g_t1[64];
__device__ float g_s2[128], g_t2[128];

// ---------------- zero accumulators (graph-replay safe) ----------------
__global__ void zero_kernel() {
    int t = threadIdx.x;
    if (t < 64) { g_sum0[t] = 0.f; g_sq0[t] = 0.f; g_sum1[t] = 0.f; g_sq1[t] = 0.f; }
    if (t < 128) { g_sum2[t] = 0.f; g_sq2[t] = 0.f; }
}

// ---------------- FPS: one block per batch (matched exactly: output 0 rel_err 0) ----------------
__global__ __launch_bounds__(256) void fps_kernel(const float* __restrict__ xyz,
                                                  float* __restrict__ out) {
    __shared__ unsigned long long s_wkey[8];
    __shared__ int s_cur;
    __shared__ int s_idx[SS];

    const int b = blockIdx.x;
    const int tid = threadIdx.x;
    const float* px = xyz + (size_t)b * 3 * NN;
    const float* py = px + NN;
    const float* pz = px + 2 * NN;

    const int base = tid * 16;
    float X[16], Y[16], Z[16], D[16];
#pragma unroll
    for (int j = 0; j < 16; j++) {
        X[j] = px[base + j]; Y[j] = py[base + j]; Z[j] = pz[base + j];
        D[j] = 1e10f;
    }

    int cur = 0;
    for (int it = 0; it < SS; it++) {
        if (tid == 0) s_idx[it] = cur;
        float cx = px[cur], cy = py[cur], cz = pz[cur];

        float bestv = -1.0f; int bestj = base;
#pragma unroll
        for (int j = 0; j < 16; j++) {
            float dx = X[j] - cx, dy = Y[j] - cy, dz = Z[j] - cz;
            float d = dx * dx + dy * dy + dz * dz;
            float nd = fminf(D[j], d);
            D[j] = nd;
            if (nd > bestv) { bestv = nd; bestj = base + j; }  // strict > => first max
        }
        unsigned long long key =
            (((unsigned long long)__float_as_uint(bestv)) << 32) | (unsigned)(~bestj);
#pragma unroll
        for (int o = 16; o > 0; o >>= 1) {
            unsigned long long other = __shfl_xor_sync(0xffffffffu, key, o);
            key = key > other ? key : other;
        }
        if ((tid & 31) == 0) s_wkey[tid >> 5] = key;
        __syncthreads();
        if (tid == 0) {
            unsigned long long m = s_wkey[0];
#pragma unroll
            for (int w = 1; w < 8; w++) m = m > s_wkey[w] ? m : s_wkey[w];
            s_cur = (int)(~(unsigned)m);
        }
        __syncthreads();
        cur = s_cur;
    }

    for (int s = tid; s < SS; s += 256) {
        int i = s_idx[s];
        float cx = px[i], cy = py[i], cz = pz[i];
        g_newxyz[b][s][0] = cx; g_newxyz[b][s][1] = cy; g_newxyz[b][s][2] = cz;
        out[(size_t)b * 3 * SS + s]          = cx;
        out[(size_t)b * 3 * SS + SS + s]     = cy;
        out[(size_t)b * 3 * SS + 2 * SS + s] = cz;
    }
}

// ---------------- ball query + grouping: exact fp32, warp per centroid ----------------
__global__ __launch_bounds__(256) void ball_group_kernel(const float* __restrict__ xyz,
                                                         const float* __restrict__ feat) {
    __shared__ int nbr[8][KK];
    const int tid = threadIdx.x;
    const int w = tid >> 5, lane = tid & 31;
    const int gw = blockIdx.x * 8 + w;
    const int b = gw >> 10, s = gw & 1023;

    const float* px = xyz + (size_t)b * 3 * NN;
    const float* py = px + NN;
    const float* pz = px + 2 * NN;

    const float cx = g_newxyz[b][s][0];
    const float cy = g_newxyz[b][s][1];
    const float cz = g_newxyz[b][s][2];
    // sn = ((cx^2 + cy^2) + cz^2) — plain fp32, no contraction
    const float sn = __fadd_rn(__fadd_rn(__fmul_rn(cx, cx), __fmul_rn(cy, cy)),
                               __fmul_rn(cz, cz));

    int cnt = 0;
    for (int c0 = 0; c0 < NN && cnt < KK; c0 += 32) {
        int n = c0 + lane;
        float x = px[n], y = py[n], z = pz[n];
        float xn = __fadd_rn(__fadd_rn(__fmul_rn(x, x), __fmul_rn(y, y)),
                             __fmul_rn(z, z));
        float dt = __fadd_rn(__fadd_rn(__fmul_rn(cx, x), __fmul_rn(cy, y)),
                             __fmul_rn(cz, z));
        float sqr = __fsub_rn(__fadd_rn(sn, xn), __fmul_rn(2.0f, dt));
        bool isin = !(sqr > 0.04f);                  // NOT(sqr > r^2), r^2 = f32(0.04)
        unsigned m = __ballot_sync(0xffffffffu, isin);
        if (isin) {
            int slot = cnt + __popc(m & ((1u << lane) - 1u));
            if (slot < KK) nbr[w][slot] = n;
        }
        cnt += __popc(m);
    }
    __syncwarp();
    int eff = cnt < KK ? cnt : KK;
    int first = nbr[w][0];
    int myn = (lane < eff) ? nbr[w][lane] : first;   // pad with first neighbor

    float gx = px[myn] - cx, gy = py[myn] - cy, gz = pz[myn] - cz;
    const float* f = feat + (size_t)b * 3 * NN;
    float f0 = f[myn], f1 = f[NN + myn], f2 = f[2 * NN + myn];

    size_t pos = ((size_t)gw) * KK + lane;
    g_G[0][pos] = gx; g_G[1][pos] = gy; g_G[2][pos] = gz;
    g_G[3][pos] = f0; g_G[4][pos] = f1; g_G[5][pos] = f2;
}

// ---------------- layer0 GEMM: 6 -> 64 (bias cancels in BN) ----------------
__global__ __launch_bounds__(256) void gemm0_kernel(const float* __restrict__ W) {
    __shared__ float w[64][6];
    const int tid = threadIdx.x;
    // FIX (round 5 bug): 384 elements, 256 threads -> strided loop, not `if (tid<384)`
    for (int e = tid; e < 384; e += 256) ((float*)w)[e] = W[e];
    __syncthreads();
    size_t pos = (size_t)blockIdx.x * 256 + tid;
    float g0 = g_G[0][pos], g1 = g_G[1][pos], g2 = g_G[2][pos];
    float g3 = g_G[3][pos], g4 = g_G[4][pos], g5 = g_G[5][pos];
#pragma unroll
    for (int o = 0; o < 64; o++) {
        float a = w[o][0] * g0;
        a = fmaf(w[o][1], g1, a);
        a = fmaf(w[o][2], g2, a);
        a = fmaf(w[o][3], g3, a);
        a = fmaf(w[o][4], g4, a);
        a = fmaf(w[o][5], g5, a);
        g_x0[o][pos] = a;
    }
}

// ---------------- per-channel sum / sumsq reduction ----------------
template <int STAGE>
__global__ __launch_bounds__(256) void reduce_kernel() {
    const float* X = STAGE == 0 ? &g_x0[0][0] : (STAGE == 1 ? &g_x1[0][0] : &g_x2[0][0]);
    float* sum = STAGE == 0 ? g_sum0 : (STAGE == 1 ? g_sum1 : g_sum2);
    float* sq  = STAGE == 0 ? g_sq0  : (STAGE == 1 ? g_sq1  : g_sq2);
    const int c = blockIdx.x;
    const int chunk = blockIdx.y;                   // 32 chunks of POSN/32
    const float4* p = (const float4*)(X + (size_t)c * POSN + (size_t)chunk * (POSN / 32));
    const int tid = threadIdx.x;
    float s = 0.f, q = 0.f;
#pragma unroll
    for (int i = 0; i < 16; i++) {                  // 16 * 256 * 4 = 16384 floats
        float4 v = p[tid + i * 256];
        s += v.x + v.y + v.z + v.w;
        q = fmaf(v.x, v.x, q); q = fmaf(v.y, v.y, q);
        q = fmaf(v.z, v.z, q); q = fmaf(v.w, v.w, q);
    }
#pragma unroll
    for (int o = 16; o > 0; o >>= 1) {
        s += __shfl_xor_sync(0xffffffffu, s, o);
        q += __shfl_xor_sync(0xffffffffu, q, o);
    }
    __shared__ float bs[8], bq[8];
    if ((tid & 31) == 0) { bs[tid >> 5] = s; bq[tid >> 5] = q; }
    __syncthreads();
    if (tid == 0) {
        float S2 = 0.f, Q = 0.f;
#pragma unroll
        for (int w = 0; w < 8; w++) { S2 += bs[w]; Q += bq[w]; }
        atomicAdd(&sum[c], S2);
        atomicAdd(&sq[c], Q);
    }
}

// ---------------- fold BN into per-channel affine y = s*x + t ----------------
template <int STAGE>
__global__ void stats_kernel(const float* __restrict__ gamma, const float* __restrict__ beta) {
    constexpr int C = (STAGE == 2) ? 128 : 64;
    const float* sum = STAGE == 0 ? g_sum0 : (STAGE == 1 ? g_sum1 : g_sum2);
    const float* sq  = STAGE == 0 ? g_sq0  : (STAGE == 1 ? g_sq1  : g_sq2);
    float* Sv = STAGE == 0 ? g_s0 : (STAGE == 1 ? g_s1 : g_s2);
    float* Tv = STAGE == 0 ? g_t0 : (STAGE == 1 ? g_t1 : g_t2);
    int c = threadIdx.x;
    if (c < C) {
        const float inv = 1.0f / (float)POSN;       // POSN = 2^19, exact
        float m = sum[c] * inv;
        float var = fmaf(-m, m, sq[c] * inv);
        if (var < 0.f) var = 0.f;
        float rs = 1.0f / sqrtf(var + 1e-5f);
        float sc = rs * gamma[c];
        Sv[c] = sc;
        Tv[c] = fmaf(-m, sc, beta[c]);              // conv bias cancels exactly
    }
}

// ---------------- fused relu(affine) + GEMM (64 -> COUT), per-position ----------------
template <int STAGE>
__global__ __launch_bounds__(256) void gemm_relu_kernel(const float* __restrict__ W) {
    constexpr int COUT = (STAGE == 1) ? 64 : 128;
    const float* X = (STAGE == 1) ? &g_x0[0][0] : &g_x1[0][0];
    float* Y       = (STAGE == 1) ? &g_x1[0][0] : &g_x2[0][0];
    const float* Sg = (STAGE == 1) ? g_s0 : g_s1;
    const float* Tg = (STAGE == 1) ? g_t0 : g_t1;

    __shared__ float Wt[64 * COUT];                 // transposed: Wt[i*COUT+o]
    __shared__ float ss[64], tt[64];
    const int tid = threadIdx.x;
    for (int e = tid; e < 64 * COUT; e += 256) {
        int i = e / COUT, o = e - i * COUT;
        Wt[e] = W[o * 64 + i];
    }
    if (tid < 64) { ss[tid] = Sg[tid]; tt[tid] = Tg[tid]; }
    __syncthreads();

    size_t pos = (size_t)blockIdx.x * 256 + tid;
    float y[64];
#pragma unroll
    for (int i = 0; i < 64; i++)
        y[i] = fmaxf(fmaf(ss[i], X[(size_t)i * POSN + pos], tt[i]), 0.0f);

#pragma unroll 1
    for (int pass = 0; pass < COUT / 16; pass++) {
        float acc[16];
#pragma unroll
        for (int j = 0; j < 16; j++) acc[j] = 0.0f;
        const float* wp = Wt + pass * 16;
#pragma unroll
        for (int i = 0; i < 64; i++) {
            float yi = y[i];
#pragma unroll
            for (int j = 0; j < 16; j++)
                acc[j] = fmaf(wp[i * COUT + j], yi, acc[j]);
        }
        float* yo = Y + (size_t)(pass * 16) * POSN + pos;
#pragma unroll
        for (int j = 0; j < 16; j++) yo[(size_t)j * POSN] = acc[j];
    }
}

// ---------------- final: relu(affine) + maxpool over K ----------------
__global__ __launch_bounds__(256) void final_kernel(float* __restrict__ out) {
    int idx = blockIdx.x * 256 + threadIdx.x;       // B*128*S threads
    int s = idx & (SS - 1);
    int c = (idx >> 10) & 127;
    int b = idx >> 17;
    float sc = g_s2[c], tc = g_t2[c];
    const float4* p = (const float4*)&g_x2[c][((size_t)(b * SS + s)) * KK];
    float m = -1e30f;
#pragma unroll
    for (int k = 0; k < 8; k++) {
        float4 v = p[k];
        m = fmaxf(m, fmaf(sc, v.x, tc));
        m = fmaxf(m, fmaf(sc, v.y, tc));
        m = fmaxf(m, fmaf(sc, v.z, tc));
        m = fmaxf(m, fmaf(sc, v.w, tc));
    }
    m = fmaxf(m, 0.0f);                             // max_k relu(a_k) = relu(max_k a_k)
    out[XYZ_OUT + ((size_t)(b * 128 + c)) * SS + s] = m;
}

// ---------------- launch ----------------
extern "C" void kernel_launch(void* const* d_in, const int* in_sizes, int n_in,
                              void* d_out, int out_size) {
    const float* xyz  = (const float*)d_in[0];
    const float* feat = (const float*)d_in[1];
    const float* w0   = (const float*)d_in[2];
    const float* g0   = (const float*)d_in[4];
    const float* bt0  = (const float*)d_in[5];
    const float* w1   = (const float*)d_in[6];
    const float* g1   = (const float*)d_in[8];
    const float* bt1  = (const float*)d_in[9];
    const float* w2   = (const float*)d_in[10];
    const float* g2   = (const float*)d_in[12];
    const float* bt2  = (const float*)d_in[13];
    float* out = (float*)d_out;

    zero_kernel<<<1, 128>>>();
    fps_kernel<<<BB, 256>>>(xyz, out);
    ball_group_kernel<<<(BB * SS) / 8, 256>>>(xyz, feat);

    gemm0_kernel<<<POSN / 256, 256>>>(w0);
    reduce_kernel<0><<<dim3(64, 32), 256>>>();
    stats_kernel<0><<<1, 128>>>(g0, bt0);

    gemm_relu_kernel<1><<<POSN / 256, 256>>>(w1);
    reduce_kernel<1><<<dim3(64, 32), 256>>>();
    stats_kernel<1><<<1, 128>>>(g1, bt1);

    gemm_relu_kernel<2><<<POSN / 256, 256>>>(w2);
    reduce_kernel<2><<<dim3(128, 32), 256>>>();
    stats_kernel<2><<<1, 128>>>(g2, bt2);

    final_kernel<<<(BB * 128 * SS) / 256, 256>>>(out);
}

// round 7
// speedup vs baseline: 1.0358x; 1.0358x over previous
#include <cuda_runtime.h>

#define BB 16
#define NN 4096
#define SS 1024
#define KK 32
#define POSN (BB*SS*KK)          // 524288
#define NGRP (BB*SS)             // 16384 (b,s) groups
#define XYZ_OUT (BB*3*SS)        // 49152

// ---------------- packed f32x2 helpers ----------------
union U2 { unsigned long long u; float2 f; };

__device__ __forceinline__ unsigned long long pack2(float lo, float hi) {
    U2 t; t.f.x = lo; t.f.y = hi; return t.u;
}
__device__ __forceinline__ void ffma2(unsigned long long& d, unsigned long long a,
                                      unsigned long long b) {
    asm("fma.rn.f32x2 %0, %1, %2, %0;" : "+l"(d) : "l"(a), "l"(b));
}
__device__ __forceinline__ unsigned long long add2(unsigned long long a, unsigned long long b) {
    unsigned long long r; asm("add.rn.f32x2 %0, %1, %2;" : "=l"(r) : "l"(a), "l"(b)); return r;
}
__device__ __forceinline__ unsigned long long mul2(unsigned long long a, unsigned long long b) {
    unsigned long long r; asm("mul.rn.f32x2 %0, %1, %2;" : "=l"(r) : "l"(a), "l"(b)); return r;
}
__device__ __forceinline__ unsigned long long max2(unsigned long long a, unsigned long long b) {
    U2 x, y, r; x.u = a; y.u = b;
    r.f.x = fmaxf(x.f.x, y.f.x); r.f.y = fmaxf(x.f.y, y.f.y);
    return r.u;
}

// ---------------- scratch (__device__ globals; no allocations) ----------------
__device__ float g_newxyz[BB][SS][3];
__device__ float g_G[6][POSN];          // grouped input, channel-major
__device__ float g_x0[64][POSN];        // layer0 pre-activation
__device__ float g_x1[64][POSN];        // layer1 pre-activation
__device__ float g_m2[NGRP][128];       // per-group k-max of layer2 pre-activation
__device__ float g_sum0[64], g_sq0[64];
__device__ float g_sum1[64], g_sq1[64];
__device__ float g_sum2[128], g_sq2[128];
__device__ float g_s0[64], g_t0[64];
__device__ float g_s1[64], g_t1[64];
__device__ float g_s2[128], g_t2[128];

// ---------------- zero accumulators (graph-replay safe) ----------------
__global__ void zero_kernel() {
    int t = threadIdx.x;
    if (t < 64) { g_sum0[t] = 0.f; g_sq0[t] = 0.f; g_sum1[t] = 0.f; g_sq1[t] = 0.f; }
    if (t < 128) { g_sum2[t] = 0.f; g_sq2[t] = 0.f; }
}

// ---------------- FPS: one block per batch; redux + single-atomic index recovery ----------------
__global__ __launch_bounds__(512) void fps_kernel(const float* __restrict__ xyz,
                                                  float* __restrict__ out) {
    __shared__ float s_val[16];
    __shared__ int s_win[2];
    __shared__ int s_idx[SS];

    const int b = blockIdx.x;
    const int tid = threadIdx.x;
    const int w = tid >> 5;
    const int lane = tid & 31;
    const float* px = xyz + (size_t)b * 3 * NN;
    const float* py = px + NN;
    const float* pz = px + 2 * NN;

    const int base = tid * 8;
    float X[8], Y[8], Z[8], D[8];
#pragma unroll
    for (int j = 0; j < 8; j++) {
        X[j] = px[base + j]; Y[j] = py[base + j]; Z[j] = pz[base + j];
        D[j] = 1e10f;
    }
    if (tid < 2) s_win[tid] = 0x7fffffff;
    __syncthreads();

    int cur = 0;
    for (int it = 0; it < SS; it++) {
        if (tid == 0) s_idx[it] = cur;
        float cx = px[cur], cy = py[cur], cz = pz[cur];

        float bv = -1.0f;
#pragma unroll
        for (int j = 0; j < 8; j++) {
            float dx = X[j] - cx, dy = Y[j] - cy, dz = Z[j] - cz;
            float d = dx * dx + dy * dy + dz * dz;          // verbatim round-6 arithmetic
            float nd = fminf(D[j], d);
            D[j] = nd;
            bv = fmaxf(bv, nd);
        }
        // warp max in one instruction (all distances >= 0 => uint order == float order)
        unsigned bu = __reduce_max_sync(0xffffffffu, __float_as_uint(bv));
        if (lane == 0) s_val[w] = __uint_as_float(bu);
        __syncthreads();                                     // barrier 1

        // all threads compute the block max (16 smem broadcasts + 15 fmax)
        float gmax = s_val[0];
#pragma unroll
        for (int ww = 1; ww < 16; ww++) gmax = fmaxf(gmax, s_val[ww]);

        // exact-equality scan, descending j => smallest local index kept
        int cand = 0x7fffffff;
#pragma unroll
        for (int j = 7; j >= 0; j--)
            if (D[j] == gmax) cand = base + j;
        if (cand != 0x7fffffff) atomicMin(&s_win[it & 1], cand);
        if (tid == 0) s_win[(it + 1) & 1] = 0x7fffffff;      // reset other parity (safe here)
        __syncthreads();                                     // barrier 2
        cur = s_win[it & 1];
    }

    for (int s = tid; s < SS; s += 512) {
        int i = s_idx[s];
        float cx = px[i], cy = py[i], cz = pz[i];
        g_newxyz[b][s][0] = cx; g_newxyz[b][s][1] = cy; g_newxyz[b][s][2] = cz;
        out[(size_t)b * 3 * SS + s]          = cx;
        out[(size_t)b * 3 * SS + SS + s]     = cy;
        out[(size_t)b * 3 * SS + 2 * SS + s] = cz;
    }
}

// ---------------- ball query + grouping: exact fp32, warp per centroid ----------------
__global__ __launch_bounds__(256) void ball_group_kernel(const float* __restrict__ xyz,
                                                         const float* __restrict__ feat) {
    __shared__ int nbr[8][KK];
    const int tid = threadIdx.x;
    const int w = tid >> 5, lane = tid & 31;
    const int gw = blockIdx.x * 8 + w;
    const int b = gw >> 10, s = gw & 1023;

    const float* px = xyz + (size_t)b * 3 * NN;
    const float* py = px + NN;
    const float* pz = px + 2 * NN;

    const float cx = g_newxyz[b][s][0];
    const float cy = g_newxyz[b][s][1];
    const float cz = g_newxyz[b][s][2];
    const float sn = __fadd_rn(__fadd_rn(__fmul_rn(cx, cx), __fmul_rn(cy, cy)),
                               __fmul_rn(cz, cz));

    int cnt = 0;
    for (int c0 = 0; c0 < NN && cnt < KK; c0 += 32) {
        int n = c0 + lane;
        float x = px[n], y = py[n], z = pz[n];
        float xn = __fadd_rn(__fadd_rn(__fmul_rn(x, x), __fmul_rn(y, y)),
                             __fmul_rn(z, z));
        float dt = __fadd_rn(__fadd_rn(__fmul_rn(cx, x), __fmul_rn(cy, y)),
                             __fmul_rn(cz, z));
        float sqr = __fsub_rn(__fadd_rn(sn, xn), __fmul_rn(2.0f, dt));
        bool isin = !(sqr > 0.04f);
        unsigned m = __ballot_sync(0xffffffffu, isin);
        if (isin) {
            int slot = cnt + __popc(m & ((1u << lane) - 1u));
            if (slot < KK) nbr[w][slot] = n;
        }
        cnt += __popc(m);
    }
    __syncwarp();
    int eff = cnt < KK ? cnt : KK;
    int first = nbr[w][0];
    int myn = (lane < eff) ? nbr[w][lane] : first;

    float gx = px[myn] - cx, gy = py[myn] - cy, gz = pz[myn] - cz;
    const float* f = feat + (size_t)b * 3 * NN;
    float f0 = f[myn], f1 = f[NN + myn], f2 = f[2 * NN + myn];

    size_t pos = ((size_t)gw) * KK + lane;
    g_G[0][pos] = gx; g_G[1][pos] = gy; g_G[2][pos] = gz;
    g_G[3][pos] = f0; g_G[4][pos] = f1; g_G[5][pos] = f2;
}

// ---------------- layer0 GEMM: 6 -> 64 ----------------
__global__ __launch_bounds__(256) void gemm0_kernel(const float* __restrict__ W) {
    __shared__ float w[64][6];
    const int tid = threadIdx.x;
    for (int e = tid; e < 384; e += 256) ((float*)w)[e] = W[e];
    __syncthreads();
    size_t pos = (size_t)blockIdx.x * 256 + tid;
    float g0 = g_G[0][pos], g1 = g_G[1][pos], g2 = g_G[2][pos];
    float g3 = g_G[3][pos], g4 = g_G[4][pos], g5 = g_G[5][pos];
#pragma unroll
    for (int o = 0; o < 64; o++) {
        float a = w[o][0] * g0;
        a = fmaf(w[o][1], g1, a);
        a = fmaf(w[o][2], g2, a);
        a = fmaf(w[o][3], g3, a);
        a = fmaf(w[o][4], g4, a);
        a = fmaf(w[o][5], g5, a);
        g_x0[o][pos] = a;
    }
}

// ---------------- per-channel sum / sumsq reduction (stages 0,1) ----------------
template <int STAGE>
__global__ __launch_bounds__(256) void reduce_kernel() {
    const float* X = STAGE == 0 ? &g_x0[0][0] : &g_x1[0][0];
    float* sum = STAGE == 0 ? g_sum0 : g_sum1;
    float* sq  = STAGE == 0 ? g_sq0  : g_sq1;
    const int c = blockIdx.x;
    const int chunk = blockIdx.y;
    const float4* p = (const float4*)(X + (size_t)c * POSN + (size_t)chunk * (POSN / 32));
    const int tid = threadIdx.x;
    float s = 0.f, q = 0.f;
#pragma unroll
    for (int i = 0; i < 16; i++) {
        float4 v = p[tid + i * 256];
        s += v.x + v.y + v.z + v.w;
        q = fmaf(v.x, v.x, q); q = fmaf(v.y, v.y, q);
        q = fmaf(v.z, v.z, q); q = fmaf(v.w, v.w, q);
    }
#pragma unroll
    for (int o = 16; o > 0; o >>= 1) {
        s += __shfl_xor_sync(0xffffffffu, s, o);
        q += __shfl_xor_sync(0xffffffffu, q, o);
    }
    __shared__ float bs[8], bq[8];
    if ((tid & 31) == 0) { bs[tid >> 5] = s; bq[tid >> 5] = q; }
    __syncthreads();
    if (tid == 0) {
        float S2 = 0.f, Q = 0.f;
#pragma unroll
        for (int w = 0; w < 8; w++) { S2 += bs[w]; Q += bq[w]; }
        atomicAdd(&sum[c], S2);
        atomicAdd(&sq[c], Q);
    }
}

// ---------------- fold BN into per-channel affine ----------------
template <int STAGE>
__global__ void stats_kernel(const float* __restrict__ gamma, const float* __restrict__ beta) {
    constexpr int C = (STAGE == 2) ? 128 : 64;
    const float* sum = STAGE == 0 ? g_sum0 : (STAGE == 1 ? g_sum1 : g_sum2);
    const float* sq  = STAGE == 0 ? g_sq0  : (STAGE == 1 ? g_sq1  : g_sq2);
    float* Sv = STAGE == 0 ? g_s0 : (STAGE == 1 ? g_s1 : g_s2);
    float* Tv = STAGE == 0 ? g_t0 : (STAGE == 1 ? g_t1 : g_t2);
    int c = threadIdx.x;
    if (c < C) {
        const float inv = 1.0f / (float)POSN;
        float m = sum[c] * inv;
        float var = fmaf(-m, m, sq[c] * inv);
        if (var < 0.f) var = 0.f;
        float rs = 1.0f / sqrtf(var + 1e-5f);
        float sc = rs * gamma[c];
        Sv[c] = sc;
        Tv[c] = fmaf(-m, sc, beta[c]);
    }
}

// ---------------- gemm1: relu(affine0) -> 64ch GEMM, f32x2, writes x1 ----------------
__global__ __launch_bounds__(256) void gemm1_kernel(const float* __restrict__ W) {
    __shared__ float Wt[64 * 64];                   // Wt[i*64+o]
    __shared__ float ss[64], tt[64];
    const int tid = threadIdx.x;
    for (int e = tid; e < 64 * 64; e += 256) {
        int i = e >> 6, o = e & 63;
        Wt[e] = W[o * 64 + i];
    }
    if (tid < 64) { ss[tid] = g_s0[tid]; tt[tid] = g_t0[tid]; }
    __syncthreads();

    size_t pos = (size_t)blockIdx.x * 256 + tid;
    float y[64];
#pragma unroll
    for (int i = 0; i < 64; i++)
        y[i] = fmaxf(fmaf(ss[i], g_x0[i][pos], tt[i]), 0.0f);

#pragma unroll 1
    for (int pass = 0; pass < 2; pass++) {
        unsigned long long acc2[16];
#pragma unroll
        for (int jp = 0; jp < 16; jp++) acc2[jp] = 0ull;
        const float* wp = Wt + pass * 32;
#pragma unroll 8
        for (int i = 0; i < 64; i++) {
            unsigned long long y2 = pack2(y[i], y[i]);
            const unsigned long long* wv = (const unsigned long long*)(wp + i * 64);
#pragma unroll
            for (int jp = 0; jp < 16; jp++) ffma2(acc2[jp], wv[jp], y2);
        }
#pragma unroll
        for (int jp = 0; jp < 16; jp++) {
            U2 u; u.u = acc2[jp];
            int c0 = pass * 32 + 2 * jp;
            g_x1[c0][pos]     = u.f.x;
            g_x1[c0 + 1][pos] = u.f.y;
        }
    }
}

// ---------------- gemm2: relu(affine1) -> 128ch GEMM, f32x2, fused sums + k-max ----------------
__global__ __launch_bounds__(256) void gemm2_kernel(const float* __restrict__ W) {
    __shared__ float Wt[64 * 128];                  // 32KB: Wt[i*128+o]
    __shared__ float ss[64], tt[64];
    __shared__ float s_sumf[8][128];
    __shared__ float s_sqf[8][128];
    const int tid = threadIdx.x;
    const int w = tid >> 5, lane = tid & 31;
    for (int e = tid; e < 64 * 128; e += 256) {
        int i = e >> 7, o = e & 127;
        Wt[e] = W[o * 64 + i];
    }
    if (tid < 64) { ss[tid] = g_s1[tid]; tt[tid] = g_t1[tid]; }
    __syncthreads();

    size_t pos = (size_t)blockIdx.x * 256 + tid;
    const int group = (int)(pos >> 5);              // warp == one (b,s) group
    float y[64];
#pragma unroll
    for (int i = 0; i < 64; i++)
        y[i] = fmaxf(fmaf(ss[i], g_x1[i][pos], tt[i]), 0.0f);

#pragma unroll 1
    for (int pass = 0; pass < 4; pass++) {
        unsigned long long acc2[16];
#pragma unroll
        for (int jp = 0; jp < 16; jp++) acc2[jp] = 0ull;
        const float* wp = Wt + pass * 32;
#pragma unroll 8
        for (int i = 0; i < 64; i++) {
            unsigned long long y2 = pack2(y[i], y[i]);
            const unsigned long long* wv = (const unsigned long long*)(wp + i * 128);
#pragma unroll
            for (int jp = 0; jp < 16; jp++) ffma2(acc2[jp], wv[jp], y2);
        }
        // fused epilogue: per channel-pair butterfly sum / sumsq / max over the 32 k-lanes
#pragma unroll
        for (int jp = 0; jp < 16; jp++) {
            unsigned long long sv = acc2[jp];
            unsigned long long qv = mul2(acc2[jp], acc2[jp]);
            unsigned long long mv = acc2[jp];
#pragma unroll
            for (int o = 16; o > 0; o >>= 1) {
                sv = add2(sv, __shfl_xor_sync(0xffffffffu, sv, o));
                qv = add2(qv, __shfl_xor_sync(0xffffffffu, qv, o));
                mv = max2(mv, __shfl_xor_sync(0xffffffffu, mv, o));
            }
            int c0 = pass * 32 + 2 * jp;
            if (lane == jp) {
                *(unsigned long long*)&s_sumf[w][c0] = sv;
                *(unsigned long long*)&s_sqf[w][c0]  = qv;
                *(unsigned long long*)&g_m2[group][c0] = mv;
            }
        }
    }
    __syncthreads();
    if (tid < 128) {
        float S = 0.f, Q = 0.f;
#pragma unroll
        for (int ww = 0; ww < 8; ww++) { S += s_sumf[ww][tid]; Q += s_sqf[ww][tid]; }
        atomicAdd(&g_sum2[tid], S);
        atomicAdd(&g_sq2[tid], Q);
    }
}

// ---------------- final: relu(affine2) on k-maxes (s2 > 0 since gamma = 1) ----------------
__global__ __launch_bounds__(256) void final_kernel(float* __restrict__ out) {
    int idx = blockIdx.x * 256 + threadIdx.x;       // B*128*S threads
    int s = idx & (SS - 1);
    int c = (idx >> 10) & 127;
    int b = idx >> 17;
    float v = g_m2[(b << 10) + s][c];
    float m = fmaxf(fmaf(g_s2[c], v, g_t2[c]), 0.0f);
    out[XYZ_OUT + ((size_t)(b * 128 + c)) * SS + s] = m;
}

// ---------------- launch ----------------
extern "C" void kernel_launch(void* const* d_in, const int* in_sizes, int n_in,
                              void* d_out, int out_size) {
    const float* xyz  = (const float*)d_in[0];
    const float* feat = (const float*)d_in[1];
    const float* w0   = (const float*)d_in[2];
    const float* g0   = (const float*)d_in[4];
    const float* bt0  = (const float*)d_in[5];
    const float* w1   = (const float*)d_in[6];
    const float* g1   = (const float*)d_in[8];
    const float* bt1  = (const float*)d_in[9];
    const float* w2   = (const float*)d_in[10];
    const float* g2   = (const float*)d_in[12];
    const float* bt2  = (const float*)d_in[13];
    float* out = (float*)d_out;

    zero_kernel<<<1, 128>>>();
    fps_kernel<<<BB, 512>>>(xyz, out);
    ball_group_kernel<<<(BB * SS) / 8, 256>>>(xyz, feat);

    gemm0_kernel<<<POSN / 256, 256>>>(w0);
    reduce_kernel<0><<<dim3(64, 32), 256>>>();
    stats_kernel<0><<<1, 128>>>(g0, bt0);

    gemm1_kernel<<<POSN / 256, 256>>>(w1);
    reduce_kernel<1><<<dim3(64, 32), 256>>>();
    stats_kernel<1><<<1, 128>>>(g1, bt1);

    gemm2_kernel<<<POSN / 256, 256>>>(w2);
    stats_kernel<2><<<1, 128>>>(g2, bt2);

    final_kernel<<<(BB * 128 * SS) / 256, 256>>>(out);
}